// round 12
// baseline (speedup 1.0000x reference)
#include <cuda_runtime.h>
#include <math.h>
#include <float.h>

#define BB 8192
#define CC 5000
#define KTOP 20
#define C4 1250              // CC/4 float4 columns
#define ROWS_PER_BLK 32
#define GY (BB/ROWS_PER_BLK) // 256
#define GX 5                 // ceil(1250/256)
#define TOTAL_BCE (GX*GY)    // 1280
#define TPB 256
#define HB (BB+1)            // histogram bins 0..8192
#define NCMAX 64
#define MW (BB/32)           // 256 mask words per class
#define NBIN 1024            // radix-select bins (float bits >> 20, values in [0,1])

__device__ float  g_counts[CC];
__device__ double g_bce;
__device__ double g_dp;
__device__ double g_dn;
__device__ int    g_nidx;
__device__ int    g_done1;
__device__ int    g_done2;
__device__ int    g_idxs[CC];
__device__ float  g_pmat[NCMAX * BB];      // sigmoid(logits) per minority class
__device__ unsigned g_tmask[NCMAX * MW];   // target==1 bitmask per minority class

// ---------------- init: zero accumulators (graph replays!) ----------------
__global__ void k_init() {
    int i = blockIdx.x * blockDim.x + threadIdx.x;
    for (; i < CC; i += gridDim.x * blockDim.x) g_counts[i] = 0.0f;
    if (blockIdx.x == 0 && threadIdx.x == 0) {
        g_bce = 0.0; g_dp = 0.0; g_dn = 0.0;
        g_nidx = 0; g_done1 = 0; g_done2 = 0;
    }
}

__device__ __forceinline__ float belem(float x, float t) {
    return fmaxf(x, 0.f) - x * t + __logf(1.f + __expf(-fabsf(x)));
}

// ------ minority-class selection, run by the LAST bce block (256 thr) -----
__device__ void do_select(int tid) {
    __shared__ int hist[HB];               // 32772 B
    __shared__ unsigned short cnts[CC];    // 10000 B
    __shared__ long long wsum[TPB];
    __shared__ int eqc[TPB];
    __shared__ int eqbase[TPB];
    __shared__ int s_vstar, s_m;

    for (int i = tid; i < HB; i += TPB) hist[i] = 0;
    __syncthreads();
    for (int j = tid; j < CC; j += TPB) {
        int c = (int)(g_counts[j] + 0.5f);
        cnts[j] = (unsigned short)c;
        atomicAdd(&hist[c], 1);
    }
    __syncthreads();

    const int CH = (HB + TPB - 1) / TPB;  // 33
    {
        int lo = tid * CH, hi = min(lo + CH, HB);
        long long loc = 0;
        for (int v = lo; v < hi; v++) loc += (long long)v * hist[v];
        wsum[tid] = loc;
    }
    __syncthreads();
    if (tid == 0) {
        const long long T = BB / 2;
        long long run = 0;
        int bchunk = -1;
        for (int t = 0; t < TPB; t++) {
            if (run + wsum[t] > T) { bchunk = t; break; }
            run += wsum[t];
        }
        s_vstar = HB; s_m = 0;
        if (bchunk >= 0) {
            int l2 = bchunk * CH, h2 = min(l2 + CH, HB);
            for (int v = l2; v < h2; v++) {
                long long w = (long long)v * hist[v];
                if (run + w > T) {
                    s_vstar = v;
                    s_m = (int)((T - run) / v);
                    break;
                }
                run += w;
            }
        }
    }
    __syncthreads();
    int vstar = s_vstar, m = s_m;

    const int CJ = (CC + TPB - 1) / TPB;  // 20
    int jlo = tid * CJ, jhi = min(jlo + CJ, CC);
    int ec = 0;
    for (int j = jlo; j < jhi; j++) if ((int)cnts[j] == vstar) ec++;
    eqc[tid] = ec;
    __syncthreads();
    if (tid == 0) {
        int a = 0;
        for (int t = 0; t < TPB; t++) { eqbase[t] = a; a += eqc[t]; }
    }
    __syncthreads();
    int base = eqbase[tid], seen = 0;
    for (int j = jlo; j < jhi; j++) {
        int c = (int)cnts[j];
        bool kept;
        if (c < vstar) kept = true;
        else if (c == vstar) { kept = (base + seen) < m; seen++; }
        else kept = false;
        if (kept && c > 1) {
            int slot = atomicAdd(&g_nidx, 1);
            if (slot < NCMAX) g_idxs[slot] = j;
        }
    }
}

// ---- fused BCE sum + per-column counts; last block runs selection --------
__global__ void __launch_bounds__(TPB, 4) k_bce_sel(
        const float4* __restrict__ lg, const float4* __restrict__ tg) {
    __shared__ float s_w[8];
    __shared__ int s_last;
    int tid = threadIdx.x;
    int c4 = blockIdx.x * TPB + tid;
    float b0 = 0.f, b1 = 0.f, b2 = 0.f, b3 = 0.f;
    float c0 = 0.f, c1 = 0.f, c2 = 0.f, c3 = 0.f;
    if (c4 < C4) {
        int r0 = blockIdx.y * ROWS_PER_BLK;
        const float4* lp = lg + (size_t)r0 * C4 + c4;
        const float4* tp = tg + (size_t)r0 * C4 + c4;
        #pragma unroll
        for (int rr = 0; rr < ROWS_PER_BLK; rr += 4) {
            float4 x0 = lp[0 * C4], x1 = lp[1 * C4], x2 = lp[2 * C4], x3 = lp[3 * C4];
            float4 t0 = tp[0 * C4], t1 = tp[1 * C4], t2 = tp[2 * C4], t3 = tp[3 * C4];
            lp += 4 * C4; tp += 4 * C4;
            b0 += belem(x0.x, t0.x) + belem(x0.y, t0.y) + belem(x0.z, t0.z) + belem(x0.w, t0.w);
            b1 += belem(x1.x, t1.x) + belem(x1.y, t1.y) + belem(x1.z, t1.z) + belem(x1.w, t1.w);
            b2 += belem(x2.x, t2.x) + belem(x2.y, t2.y) + belem(x2.z, t2.z) + belem(x2.w, t2.w);
            b3 += belem(x3.x, t3.x) + belem(x3.y, t3.y) + belem(x3.z, t3.z) + belem(x3.w, t3.w);
            c0 += t0.x + t1.x + t2.x + t3.x;
            c1 += t0.y + t1.y + t2.y + t3.y;
            c2 += t0.z + t1.z + t2.z + t3.z;
            c3 += t0.w + t1.w + t2.w + t3.w;
        }
        atomicAdd(&g_counts[c4 * 4 + 0], c0);
        atomicAdd(&g_counts[c4 * 4 + 1], c1);
        atomicAdd(&g_counts[c4 * 4 + 2], c2);
        atomicAdd(&g_counts[c4 * 4 + 3], c3);
    }
    float bce = (b0 + b1) + (b2 + b3);
    int lane = tid & 31, wid = tid >> 5;
    #pragma unroll
    for (int o = 16; o > 0; o >>= 1) bce += __shfl_down_sync(0xffffffffu, bce, o);
    if (lane == 0) s_w[wid] = bce;
    __syncthreads();
    if (tid == 0) {
        float a = 0.f;
        #pragma unroll
        for (int w = 0; w < 8; w++) a += s_w[w];
        atomicAdd(&g_bce, (double)a);
    }
    // last-block ticket -> run selection inline (saves a launch)
    __threadfence();
    if (tid == 0) {
        int t = atomicAdd(&g_done1, 1);
        s_last = (t == TOTAL_BCE - 1) ? 1 : 0;
    }
    __syncthreads();
    if (s_last) {
        __threadfence();
        do_select(tid);
    }
}

// ----------- massively parallel gather: sigmoid + target bitmask ----------
__global__ void k_gather(const float* __restrict__ lg, const float* __restrict__ tg) {
    int ci = blockIdx.x;
    if (ci >= g_nidx) return;
    int j = g_idxs[ci];
    int r = blockIdx.y * TPB + threadIdx.x;
    float x = lg[(size_t)r * CC + j];
    float t = tg[(size_t)r * CC + j];
    float p = 1.0f / (1.0f + __expf(-x));
    g_pmat[ci * BB + r] = p;
    unsigned m = __ballot_sync(0xffffffffu, t == 1.0f);
    if ((threadIdx.x & 31) == 0) g_tmask[ci * MW + (r >> 5)] = m;
}

// ---- radix-select k smallest among {i : posflag(i)==want_pos}, sorted ----
__device__ __forceinline__ void select_k(int* h, const float* s_v,
                                         const unsigned* s_m, int want_pos,
                                         int k, float* out, int* chunk,
                                         int* s_cnt, int* s_bin) {
    int tid = threadIdx.x;
    int base = tid * (NBIN / TPB);  // 4 bins/thread
    chunk[tid] = h[base] + h[base + 1] + h[base + 2] + h[base + 3];
    __syncthreads();
    if (tid == 0) {
        int run = 0, t = 0;
        while (run + chunk[t] < k) { run += chunk[t]; t++; }
        int b = t * (NBIN / TPB);
        while (run + h[b] < k) { run += h[b]; b++; }
        *s_bin = b;
        *s_cnt = 0;
    }
    __syncthreads();
    unsigned B = (unsigned)*s_bin;
    float* cand = (float*)h;   // reuse histogram memory
    __syncthreads();
    for (int i = tid; i < BB; i += TPB) {
        int pos = (s_m[i >> 5] >> (i & 31)) & 1;
        if (pos == want_pos) {
            float v = s_v[i];
            if ((__float_as_uint(v) >> 20) <= B) {
                int id = atomicAdd(s_cnt, 1);
                if (id < NBIN) cand[id] = v;
            }
        }
    }
    __syncthreads();
    int n = min(*s_cnt, NBIN);
    for (int i = tid; i < n; i += TPB) {
        float vi = cand[i];
        int r = 0;
        for (int j = 0; j < n; j++) {
            float vj = cand[j];
            r += (vj < vi) || (vj == vi && j < i);
        }
        if (r < k) out[r] = vi;
    }
    __syncthreads();
}

// -- per-class radix-select & closed-form sums; last block computes final --
__global__ void k_crl2_final(float* out) {
    __shared__ float    s_v[BB];        // 32 KB
    __shared__ unsigned s_m[MW];        // 1 KB
    __shared__ int      h_pos[NBIN];    // 4 KB (reused as cand buffer)
    __shared__ int      h_neg[NBIN];    // 4 KB (reused as cand buffer)
    __shared__ int      chunk[TPB];     // 1 KB
    __shared__ double   s_rd[8];
    __shared__ int      s_rc[8];
    __shared__ float    s_rf[8];
    __shared__ float    s_neg[KTOP];
    __shared__ float    s_xs[KTOP + 1];
    __shared__ int      s_cnt, s_bin, s_lastc;

    int ci = blockIdx.x;
    int tid = threadIdx.x;
    int lane = tid & 31, wid = tid >> 5;

    if (ci < g_nidx) {
        for (int i = tid; i < NBIN; i += TPB) { h_pos[i] = 0; h_neg[i] = 0; }
        for (int i = tid; i < MW; i += TPB) s_m[i] = g_tmask[ci * MW + i];
        __syncthreads();

        // single pass: load s_v, warp-aggregated histograms, S and c_p
        double ls = 0.0; int lc = 0;
        for (int i = tid; i < BB; i += TPB) {   // BB%TPB==0: all lanes active
            float v = g_pmat[ci * BB + i];
            s_v[i] = v;
            unsigned b = __float_as_uint(v) >> 20;   // [0,1] -> b <= 1016
            int posf = (s_m[i >> 5] >> (i & 31)) & 1;
            if (posf) { ls += (double)v; lc++; }
            unsigned key = b | ((unsigned)posf << 12);
            unsigned mk = __match_any_sync(0xffffffffu, key);
            if (lane == (__ffs(mk) - 1))
                atomicAdd(posf ? &h_pos[b] : &h_neg[b], __popc(mk));
        }
        #pragma unroll
        for (int o = 16; o > 0; o >>= 1) {
            ls += __shfl_down_sync(0xffffffffu, ls, o);
            lc += __shfl_down_sync(0xffffffffu, lc, o);
        }
        if (lane == 0) { s_rd[wid] = ls; s_rc[wid] = lc; }
        __syncthreads();
        if (tid == 0) {
            double a = 0.0; int b = 0;
            #pragma unroll
            for (int w = 0; w < 8; w++) { a += s_rd[w]; b += s_rc[w]; }
            s_rd[0] = a; s_rc[0] = b;
        }
        __syncthreads();
        float S = (float)s_rd[0];
        int c_p = s_rc[0];

        if (c_p > 0) {
            int np_a = min(KTOP, c_p - 1);
            int n_n  = min(KTOP, BB - c_p);
            int m_p  = np_a + 1;

            if (n_n > 0)
                select_k(h_neg, s_v, s_m, 0, n_n, s_neg, chunk, &s_cnt, &s_bin);
            select_k(h_pos, s_v, s_m, 1, m_p, s_xs, chunk, &s_cnt, &s_bin);

            float nsum = 0.0f;
            if (n_n > 0) {
                for (int i = tid; i < BB; i += TPB) {
                    if ((s_m[i >> 5] >> (i & 31)) & 1u) {
                        float p = s_v[i];
                        #pragma unroll
                        for (int q = 0; q < KTOP; q++)
                            if (q < n_n) nsum += fabsf(p - s_neg[q]);
                    }
                }
            }
            #pragma unroll
            for (int o = 16; o > 0; o >>= 1) nsum += __shfl_down_sync(0xffffffffu, nsum, o);
            if (lane == 0) s_rf[wid] = nsum;
            __syncthreads();
            if (tid == 0 && n_n > 0) {
                float a = 0.0f;
                #pragma unroll
                for (int w = 0; w < 8; w++) a += s_rf[w];
                atomicAdd(&g_dn, (double)((float)np_a * a));
            }

            if (tid == 0) {
                float P[KTOP + 2];
                P[0] = 0.0f;
                for (int u = 0; u < m_p; u++) P[u + 1] = P[u] + s_xs[u];
                float pos_sum = 0.0f;
                for (int r = 0; r <= np_a; r++) {
                    pos_sum += (float)r * s_xs[r] - P[r]
                             + (P[np_a + 1] - P[r + 1])
                             - (float)(np_a - r) * s_xs[r];
                }
                if (c_p - 1 > np_a)
                    pos_sum += (float)np_a * (S - P[np_a + 1])
                             - (float)(c_p - 1 - np_a) * P[np_a];
                atomicAdd(&g_dp, (double)((float)n_n * pos_sum));
            }
        }
    }

    // ---- all NCMAX blocks arrive; last one computes the final loss ----
    __threadfence();
    __syncthreads();
    if (tid == 0) {
        int t = atomicAdd(&g_done2, 1);
        s_lastc = (t == NCMAX - 1) ? 1 : 0;
    }
    __syncthreads();
    if (s_lastc && tid == 0) {
        __threadfence();
        double bce = g_bce / (double)((long long)BB * CC);
        float loss;
        if (g_nidx == 0) {
            loss = (float)bce;
        } else {
            double crl = g_dp - g_dn + 0.5;  // MARGIN
            if (crl < 0.0) crl = 0.0;
            loss = (float)(0.5 * crl + 0.5 * bce);  // ALPHA = 0.5
        }
        out[0] = loss;
    }
}

extern "C" void kernel_launch(void* const* d_in, const int* in_sizes, int n_in,
                              void* d_out, int out_size) {
    const float* logits = (const float*)d_in[0];
    const float* target = (const float*)d_in[1];
    float* out = (float*)d_out;

    k_init<<<20, TPB>>>();
    k_bce_sel<<<dim3(GX, GY), TPB>>>((const float4*)logits, (const float4*)target);
    k_gather<<<dim3(NCMAX, BB / TPB), TPB>>>(logits, target);
    k_crl2_final<<<NCMAX, TPB>>>(out);
}

// round 16
// speedup vs baseline: 1.0469x; 1.0469x over previous
#include <cuda_runtime.h>
#include <math.h>
#include <float.h>

#define BB 8192
#define CC 5000
#define KTOP 20
#define C4 1250              // CC/4 float4 columns
#define ROWS_PER_BLK 32
#define GY (BB/ROWS_PER_BLK) // 256
#define GX 5                 // ceil(1250/256)
#define TOTAL_BCE (GX*GY)    // 1280
#define TPB 256
#define TPB2 1024            // crl2 block size
#define NIT (BB/TPB2)        // 8 elements per thread in crl2
#define HB (BB+1)            // histogram bins 0..8192
#define NCMAX 64
#define MW (BB/32)           // 256 mask words per class
#define NBIN 1024            // radix-select bins (float bits >> 20, values in [0,1])

__device__ float  g_counts[CC];
__device__ double g_bce;
__device__ double g_dp;
__device__ double g_dn;
__device__ int    g_nidx;
__device__ int    g_done1;
__device__ int    g_done2;
__device__ int    g_idxs[CC];
__device__ float  g_pmat[NCMAX * BB];      // sigmoid(logits) per minority class
__device__ unsigned g_tmask[NCMAX * MW];   // target==1 bitmask per minority class

// ---------------- init: zero accumulators (graph replays!) ----------------
__global__ void k_init() {
    int i = blockIdx.x * blockDim.x + threadIdx.x;
    for (; i < CC; i += gridDim.x * blockDim.x) g_counts[i] = 0.0f;
    if (blockIdx.x == 0 && threadIdx.x == 0) {
        g_bce = 0.0; g_dp = 0.0; g_dn = 0.0;
        g_nidx = 0; g_done1 = 0; g_done2 = 0;
    }
}

__device__ __forceinline__ float belem(float x, float t) {
    return fmaxf(x, 0.f) - x * t + __logf(1.f + __expf(-fabsf(x)));
}

// ------ minority-class selection, run by the LAST bce block (256 thr) -----
__device__ void do_select(int tid) {
    __shared__ int hist[HB];               // 32772 B
    __shared__ unsigned short cnts[CC];    // 10000 B
    __shared__ long long wsum[TPB];
    __shared__ int eqc[TPB];
    __shared__ int eqbase[TPB];
    __shared__ int s_vstar, s_m;

    for (int i = tid; i < HB; i += TPB) hist[i] = 0;
    __syncthreads();
    for (int j = tid; j < CC; j += TPB) {
        int c = (int)(g_counts[j] + 0.5f);
        cnts[j] = (unsigned short)c;
        atomicAdd(&hist[c], 1);
    }
    __syncthreads();

    const int CH = (HB + TPB - 1) / TPB;  // 33
    {
        int lo = tid * CH, hi = min(lo + CH, HB);
        long long loc = 0;
        for (int v = lo; v < hi; v++) loc += (long long)v * hist[v];
        wsum[tid] = loc;
    }
    __syncthreads();
    if (tid == 0) {
        const long long T = BB / 2;
        long long run = 0;
        int bchunk = -1;
        for (int t = 0; t < TPB; t++) {
            if (run + wsum[t] > T) { bchunk = t; break; }
            run += wsum[t];
        }
        s_vstar = HB; s_m = 0;
        if (bchunk >= 0) {
            int l2 = bchunk * CH, h2 = min(l2 + CH, HB);
            for (int v = l2; v < h2; v++) {
                long long w = (long long)v * hist[v];
                if (run + w > T) {
                    s_vstar = v;
                    s_m = (int)((T - run) / v);
                    break;
                }
                run += w;
            }
        }
    }
    __syncthreads();
    int vstar = s_vstar, m = s_m;

    const int CJ = (CC + TPB - 1) / TPB;  // 20
    int jlo = tid * CJ, jhi = min(jlo + CJ, CC);
    int ec = 0;
    for (int j = jlo; j < jhi; j++) if ((int)cnts[j] == vstar) ec++;
    eqc[tid] = ec;
    __syncthreads();
    if (tid == 0) {
        int a = 0;
        for (int t = 0; t < TPB; t++) { eqbase[t] = a; a += eqc[t]; }
    }
    __syncthreads();
    int base = eqbase[tid], seen = 0;
    for (int j = jlo; j < jhi; j++) {
        int c = (int)cnts[j];
        bool kept;
        if (c < vstar) kept = true;
        else if (c == vstar) { kept = (base + seen) < m; seen++; }
        else kept = false;
        if (kept && c > 1) {
            int slot = atomicAdd(&g_nidx, 1);
            if (slot < NCMAX) g_idxs[slot] = j;
        }
    }
}

// ---- fused BCE sum + per-column counts; last block runs selection --------
__global__ void __launch_bounds__(TPB, 4) k_bce_sel(
        const float4* __restrict__ lg, const float4* __restrict__ tg) {
    __shared__ float s_w[8];
    __shared__ int s_last;
    int tid = threadIdx.x;
    int c4 = blockIdx.x * TPB + tid;
    float b0 = 0.f, b1 = 0.f, b2 = 0.f, b3 = 0.f;
    float c0 = 0.f, c1 = 0.f, c2 = 0.f, c3 = 0.f;
    if (c4 < C4) {
        int r0 = blockIdx.y * ROWS_PER_BLK;
        const float4* lp = lg + (size_t)r0 * C4 + c4;
        const float4* tp = tg + (size_t)r0 * C4 + c4;
        #pragma unroll
        for (int rr = 0; rr < ROWS_PER_BLK; rr += 4) {
            float4 x0 = lp[0 * C4], x1 = lp[1 * C4], x2 = lp[2 * C4], x3 = lp[3 * C4];
            float4 t0 = tp[0 * C4], t1 = tp[1 * C4], t2 = tp[2 * C4], t3 = tp[3 * C4];
            lp += 4 * C4; tp += 4 * C4;
            b0 += belem(x0.x, t0.x) + belem(x0.y, t0.y) + belem(x0.z, t0.z) + belem(x0.w, t0.w);
            b1 += belem(x1.x, t1.x) + belem(x1.y, t1.y) + belem(x1.z, t1.z) + belem(x1.w, t1.w);
            b2 += belem(x2.x, t2.x) + belem(x2.y, t2.y) + belem(x2.z, t2.z) + belem(x2.w, t2.w);
            b3 += belem(x3.x, t3.x) + belem(x3.y, t3.y) + belem(x3.z, t3.z) + belem(x3.w, t3.w);
            c0 += t0.x + t1.x + t2.x + t3.x;
            c1 += t0.y + t1.y + t2.y + t3.y;
            c2 += t0.z + t1.z + t2.z + t3.z;
            c3 += t0.w + t1.w + t2.w + t3.w;
        }
        atomicAdd(&g_counts[c4 * 4 + 0], c0);
        atomicAdd(&g_counts[c4 * 4 + 1], c1);
        atomicAdd(&g_counts[c4 * 4 + 2], c2);
        atomicAdd(&g_counts[c4 * 4 + 3], c3);
    }
    float bce = (b0 + b1) + (b2 + b3);
    int lane = tid & 31, wid = tid >> 5;
    #pragma unroll
    for (int o = 16; o > 0; o >>= 1) bce += __shfl_down_sync(0xffffffffu, bce, o);
    if (lane == 0) s_w[wid] = bce;
    __syncthreads();
    if (tid == 0) {
        float a = 0.f;
        #pragma unroll
        for (int w = 0; w < 8; w++) a += s_w[w];
        atomicAdd(&g_bce, (double)a);
    }
    // last-block ticket -> run selection inline (saves a launch)
    __threadfence();
    if (tid == 0) {
        int t = atomicAdd(&g_done1, 1);
        s_last = (t == TOTAL_BCE - 1) ? 1 : 0;
    }
    __syncthreads();
    if (s_last) {
        __threadfence();
        do_select(tid);
    }
}

// ----------- massively parallel gather: sigmoid + target bitmask ----------
__global__ void k_gather(const float* __restrict__ lg, const float* __restrict__ tg) {
    int ci = blockIdx.x;
    if (ci >= g_nidx) return;
    int j = g_idxs[ci];
    int r = blockIdx.y * TPB + threadIdx.x;
    float x = lg[(size_t)r * CC + j];
    float t = tg[(size_t)r * CC + j];
    float p = 1.0f / (1.0f + __expf(-x));
    g_pmat[ci * BB + r] = p;
    unsigned m = __ballot_sync(0xffffffffu, t == 1.0f);
    if ((threadIdx.x & 31) == 0) g_tmask[ci * MW + (r >> 5)] = m;
}

// ---- radix-select k smallest among {i : posflag(i)==want_pos}, sorted ----
// Runs at TPB2=1024 threads; chunk level stays 256-wide (4 bins/thread).
__device__ __forceinline__ void select_k(int* h, const float* s_v,
                                         const unsigned* s_m, int want_pos,
                                         int k, float* out, int* chunk,
                                         int* s_cnt, int* s_bin) {
    int tid = threadIdx.x;
    if (tid < 256) {
        int base = tid * 4;
        chunk[tid] = h[base] + h[base + 1] + h[base + 2] + h[base + 3];
    }
    __syncthreads();
    if (tid == 0) {
        int run = 0, t = 0;
        while (run + chunk[t] < k) { run += chunk[t]; t++; }
        int b = t * 4;
        while (run + h[b] < k) { run += h[b]; b++; }
        *s_bin = b;
        *s_cnt = 0;
    }
    __syncthreads();
    unsigned B = (unsigned)*s_bin;
    float* cand = (float*)h;   // reuse histogram memory
    __syncthreads();
    #pragma unroll
    for (int u = 0; u < NIT; u++) {
        int i = u * TPB2 + tid;
        int pos = (s_m[i >> 5] >> (i & 31)) & 1;
        if (pos == want_pos) {
            float v = s_v[i];
            if ((__float_as_uint(v) >> 20) <= B) {
                int id = atomicAdd(s_cnt, 1);
                if (id < NBIN) cand[id] = v;
            }
        }
    }
    __syncthreads();
    int n = min(*s_cnt, NBIN);
    for (int i = tid; i < n; i += TPB2) {
        float vi = cand[i];
        int r = 0;
        for (int j = 0; j < n; j++) {
            float vj = cand[j];
            r += (vj < vi) || (vj == vi && j < i);
        }
        if (r < k) out[r] = vi;
    }
    __syncthreads();
}

// -- per-class radix-select & closed-form sums; last block computes final --
// 1024 threads: all 8192-element loops are 8 iterations; pass-1 loads
// front-batched into registers (single latency exposure).
__global__ void __launch_bounds__(TPB2, 1) k_crl2_final(float* out) {
    __shared__ float    s_v[BB];        // 32 KB
    __shared__ unsigned s_m[MW];        // 1 KB
    __shared__ int      h_pos[NBIN];    // 4 KB (reused as cand buffer)
    __shared__ int      h_neg[NBIN];    // 4 KB (reused as cand buffer)
    __shared__ int      chunk[256];     // 1 KB
    __shared__ double   s_rd[32];
    __shared__ int      s_rc[32];
    __shared__ float    s_rf[32];
    __shared__ float    s_neg[KTOP];
    __shared__ float    s_xs[KTOP + 1];
    __shared__ int      s_cnt, s_bin, s_lastc;

    int ci = blockIdx.x;
    int tid = threadIdx.x;
    int lane = tid & 31, wid = tid >> 5;

    if (ci < g_nidx) {
        if (tid < NBIN) { h_pos[tid] = 0; h_neg[tid] = 0; }
        if (tid < MW) s_m[tid] = g_tmask[ci * MW + tid];

        // front-batched independent global loads (one latency exposure)
        const float* vp = g_pmat + ci * BB;
        float vloc[NIT];
        #pragma unroll
        for (int u = 0; u < NIT; u++) vloc[u] = vp[u * TPB2 + tid];
        __syncthreads();   // mask + zeroed histograms visible

        // histogram + S + c_p in one pass over registers
        double ls = 0.0; int lc = 0;
        #pragma unroll
        for (int u = 0; u < NIT; u++) {
            int i = u * TPB2 + tid;
            float v = vloc[u];
            s_v[i] = v;
            unsigned b = __float_as_uint(v) >> 20;   // [0,1] -> b <= 1016
            int posf = (s_m[i >> 5] >> (i & 31)) & 1;
            if (posf) { ls += (double)v; lc++; }
            unsigned key = b | ((unsigned)posf << 12);
            unsigned mk = __match_any_sync(0xffffffffu, key);
            if (lane == (__ffs(mk) - 1))
                atomicAdd(posf ? &h_pos[b] : &h_neg[b], __popc(mk));
        }
        #pragma unroll
        for (int o = 16; o > 0; o >>= 1) {
            ls += __shfl_down_sync(0xffffffffu, ls, o);
            lc += __shfl_down_sync(0xffffffffu, lc, o);
        }
        if (lane == 0) { s_rd[wid] = ls; s_rc[wid] = lc; }
        __syncthreads();
        if (tid == 0) {
            double a = 0.0; int b = 0;
            #pragma unroll
            for (int w = 0; w < 32; w++) { a += s_rd[w]; b += s_rc[w]; }
            s_rd[0] = a; s_rc[0] = b;
        }
        __syncthreads();
        float S = (float)s_rd[0];
        int c_p = s_rc[0];

        if (c_p > 0) {
            int np_a = min(KTOP, c_p - 1);
            int n_n  = min(KTOP, BB - c_p);
            int m_p  = np_a + 1;

            if (n_n > 0)
                select_k(h_neg, s_v, s_m, 0, n_n, s_neg, chunk, &s_cnt, &s_bin);
            select_k(h_pos, s_v, s_m, 1, m_p, s_xs, chunk, &s_cnt, &s_bin);

            float nsum = 0.0f;
            if (n_n > 0) {
                #pragma unroll
                for (int u = 0; u < NIT; u++) {
                    int i = u * TPB2 + tid;
                    if ((s_m[i >> 5] >> (i & 31)) & 1u) {
                        float p = s_v[i];
                        #pragma unroll
                        for (int q = 0; q < KTOP; q++)
                            if (q < n_n) nsum += fabsf(p - s_neg[q]);
                    }
                }
            }
            #pragma unroll
            for (int o = 16; o > 0; o >>= 1) nsum += __shfl_down_sync(0xffffffffu, nsum, o);
            if (lane == 0) s_rf[wid] = nsum;
            __syncthreads();
            if (tid == 0 && n_n > 0) {
                float a = 0.0f;
                #pragma unroll
                for (int w = 0; w < 32; w++) a += s_rf[w];
                atomicAdd(&g_dn, (double)((float)np_a * a));
            }

            if (tid == 0) {
                float P[KTOP + 2];
                P[0] = 0.0f;
                for (int u = 0; u < m_p; u++) P[u + 1] = P[u] + s_xs[u];
                float pos_sum = 0.0f;
                for (int r = 0; r <= np_a; r++) {
                    pos_sum += (float)r * s_xs[r] - P[r]
                             + (P[np_a + 1] - P[r + 1])
                             - (float)(np_a - r) * s_xs[r];
                }
                if (c_p - 1 > np_a)
                    pos_sum += (float)np_a * (S - P[np_a + 1])
                             - (float)(c_p - 1 - np_a) * P[np_a];
                atomicAdd(&g_dp, (double)((float)n_n * pos_sum));
            }
        }
    }

    // ---- all NCMAX blocks arrive; last one computes the final loss ----
    __threadfence();
    __syncthreads();
    if (tid == 0) {
        int t = atomicAdd(&g_done2, 1);
        s_lastc = (t == NCMAX - 1) ? 1 : 0;
    }
    __syncthreads();
    if (s_lastc && tid == 0) {
        __threadfence();
        double bce = g_bce / (double)((long long)BB * CC);
        float loss;
        if (g_nidx == 0) {
            loss = (float)bce;
        } else {
            double crl = g_dp - g_dn + 0.5;  // MARGIN
            if (crl < 0.0) crl = 0.0;
            loss = (float)(0.5 * crl + 0.5 * bce);  // ALPHA = 0.5
        }
        out[0] = loss;
    }
}

extern "C" void kernel_launch(void* const* d_in, const int* in_sizes, int n_in,
                              void* d_out, int out_size) {
    const float* logits = (const float*)d_in[0];
    const float* target = (const float*)d_in[1];
    float* out = (float*)d_out;

    k_init<<<20, TPB>>>();
    k_bce_sel<<<dim3(GX, GY), TPB>>>((const float4*)logits, (const float4*)target);
    k_gather<<<dim3(NCMAX, BB / TPB), TPB>>>(logits, target);
    k_crl2_final<<<NCMAX, TPB2>>>(out);
}